// round 3
// baseline (speedup 1.0000x reference)
#include <cuda_runtime.h>

#define NB   2
#define NE   8
#define NPX  4096      // 64*64
#define KTOP 700
#define NG   4
#define NCH  36        // (NE+1)*NG
#define OUTW 256

__device__ int g_topk_idx[NB * KTOP];

__device__ __forceinline__ float frcp(float x) {
    float r;
    asm("rcp.approx.f32 %0, %1;" : "=f"(r) : "f"(x));
    return r;
}

// ---------------------------------------------------------------------------
// Kernel 1: per-batch bitonic sort of 4096 (logit, index) pairs, descending by
// value (ties: ascending index, matching lax.top_k). Writes sorted sigmoid
// scores to d_out tail and top-700 indices to scratch.
// ---------------------------------------------------------------------------
__global__ void topk_kernel(const float* __restrict__ obj,
                            float* __restrict__ scores) {
    __shared__ float sval[NPX];
    __shared__ int   sidx[NPX];
    const int b   = blockIdx.x;
    const int tid = threadIdx.x;

    const float* p = obj + b * NPX;
    for (int i = tid; i < NPX; i += 1024) { sval[i] = p[i]; sidx[i] = i; }
    __syncthreads();

    for (int k = 2; k <= NPX; k <<= 1) {
        for (int j = k >> 1; j > 0; j >>= 1) {
            for (int i = tid; i < NPX; i += 1024) {
                const int ixj = i ^ j;
                if (ixj > i) {
                    float v1 = sval[i], v2 = sval[ixj];
                    int   i1 = sidx[i], i2 = sidx[ixj];
                    // "less" = comes-first in descending order
                    bool less12 = (v1 > v2) || (v1 == v2 && i1 < i2);
                    bool up = ((i & k) == 0);
                    if (up ? !less12 : less12) {
                        sval[i] = v2; sval[ixj] = v1;
                        sidx[i] = i2; sidx[ixj] = i1;
                    }
                }
            }
            __syncthreads();
        }
    }

    if (tid < KTOP) {
        scores[b * KTOP + tid] = frcp(1.0f + __expf(-sval[tid]));
        g_topk_idx[b * KTOP + tid] = sidx[tid];
    }
}

// ---------------------------------------------------------------------------
// Kernel 2: one block per (b, k). Phase 1: gather the 36 weights at the
// selected position, compute the 64x64 group-product mask into SMEM
//   mask = 1 / prod_g (1 + exp(-(w_g . enc + b_g)))
// Phase 2: 4x clamp-to-edge bilinear upsample to 256x256, streamed to GMEM.
// ---------------------------------------------------------------------------
__global__ __launch_bounds__(256)
void mask_kernel(const float* __restrict__ enc,   // (NB, NE, 64, 64)
                 const float* __restrict__ wts,   // (NB, NCH, 64, 64)
                 float* __restrict__ out) {       // (NB, KTOP, 256, 256)
    __shared__ float low[NPX];
    __shared__ float swt[NCH];

    const int k   = blockIdx.x;
    const int b   = blockIdx.y;
    const int tid = threadIdx.x;

    const int pos = g_topk_idx[b * KTOP + k];
    if (tid < NCH) swt[tid] = wts[(b * NCH + tid) * NPX + pos];
    __syncthreads();

    float wm[NG][NE], bias[NG];
#pragma unroll
    for (int g = 0; g < NG; g++) {
#pragma unroll
        for (int e = 0; e < NE; e++) wm[g][e] = swt[g * (NE + 1) + e];
        bias[g] = swt[g * (NE + 1) + NE];
    }

    const float* encb = enc + b * NE * NPX;
#pragma unroll
    for (int it = 0; it < 4; it++) {
        const int q = tid + it * 256;  // float4 index into the 64x64 plane
        float4 ev[NE];
#pragma unroll
        for (int e = 0; e < NE; e++)
            ev[e] = __ldg((const float4*)(encb + e * NPX) + q);

        float px = 1.f, py = 1.f, pz = 1.f, pw = 1.f;
#pragma unroll
        for (int g = 0; g < NG; g++) {
            float ax = bias[g], ay = bias[g], az = bias[g], aw = bias[g];
#pragma unroll
            for (int e = 0; e < NE; e++) {
                ax = fmaf(wm[g][e], ev[e].x, ax);
                ay = fmaf(wm[g][e], ev[e].y, ay);
                az = fmaf(wm[g][e], ev[e].z, az);
                aw = fmaf(wm[g][e], ev[e].w, aw);
            }
            px *= 1.f + __expf(-ax);
            py *= 1.f + __expf(-ay);
            pz *= 1.f + __expf(-az);
            pw *= 1.f + __expf(-aw);
        }
        float4 r = make_float4(frcp(px), frcp(py), frcp(pz), frcp(pw));
        ((float4*)low)[q] = r;
    }
    __syncthreads();

    // Phase 2: bilinear 64->256. Warp w owns output rows [32w, 32w+32);
    // lanes stride columns -> conflict-free LDS, coalesced STG.128.
    float* obase = out + ((size_t)(b * KTOP + k)) * (OUTW * OUTW);
    const int warp = tid >> 5, lane = tid & 31;

#pragma unroll 1
    for (int r = 0; r < 32; r++) {
        const int oy = warp * 32 + r;
        const float yf  = oy * 0.25f - 0.375f;
        const float y0f = floorf(yf);
        const float fy  = yf - y0f;
        int y0 = (int)y0f;     if (y0 < 0)  y0 = 0;
        int y1 = (int)y0f + 1; if (y1 > 63) y1 = 63;
        const float* r0 = low + y0 * 64;
        const float* r1 = low + y1 * 64;
        float4* orow = (float4*)(obase + oy * OUTW);
#pragma unroll
        for (int c = 0; c < 2; c++) {
            const int j  = lane + c * 32;
            const int jp = (j == 0)  ? 0  : j - 1;
            const int jn = (j == 63) ? 63 : j + 1;
            const float vp = fmaf(fy, r1[jp] - r0[jp], r0[jp]);
            const float vc = fmaf(fy, r1[j]  - r0[j],  r0[j]);
            const float vn = fmaf(fy, r1[jn] - r0[jn], r0[jn]);
            float4 o;
            o.x = 0.375f * vp + 0.625f * vc;
            o.y = 0.125f * vp + 0.875f * vc;
            o.z = 0.875f * vc + 0.125f * vn;
            o.w = 0.625f * vc + 0.375f * vn;
            __stcs(orow + j, o);
        }
    }
}

// ---------------------------------------------------------------------------
extern "C" void kernel_launch(void* const* d_in, const int* in_sizes, int n_in,
                              void* d_out, int out_size) {
    const float* obj = (const float*)d_in[0];  // objectness_logits (2,1,64,64)
    const float* enc = (const float*)d_in[1];  // mask_encodings   (2,8,64,64)
    const float* wts = (const float*)d_in[2];  // weights          (2,36,64,64)
    float* out    = (float*)d_out;             // m (2,700,256,256) then scores (2,700)
    float* scores = out + (size_t)NB * KTOP * OUTW * OUTW;

    topk_kernel<<<NB, 1024>>>(obj, scores);
    dim3 grid(KTOP, NB);
    mask_kernel<<<grid, 256>>>(enc, wts, out);
}

// round 7
// speedup vs baseline: 1.4718x; 1.4718x over previous
#include <cuda_runtime.h>

#define NB   2
#define NE   8
#define NPX  4096      // 64*64
#define KTOP 700
#define NG   4
#define NCH  36        // (NE+1)*NG
#define OUTW 256

__device__ int g_topk_idx[NB * KTOP];

__device__ __forceinline__ float frcp(float x) {
    float r;
    asm("rcp.approx.f32 %0, %1;" : "=f"(r) : "f"(x));
    return r;
}

// ---------------------------------------------------------------------------
// Kernel 1: exact top-k by parallel rank counting.
// key(e) = (monotonic(val_e), tie: smaller index first) -> all keys distinct,
// rank(e) = #{i : key_i comes before key_e in descending order}.
// Grid (64, NB), 512 threads: block caches all 4096 monotonic keys in SMEM;
// thread (e_local = tid>>3, s = tid&7) counts the slice {i : i mod 8 == s}
// (per-warp: 8 distinct banks x 4-lane broadcast -> conflict-free), then a
// 3-step shuffle tree reduces the 8 partials. rank < 700 scatters directly
// into sorted position. No sort, no cross-block sync, fully parallel.
// ---------------------------------------------------------------------------
__global__ __launch_bounds__(512)
void topk_rank_kernel(const float* __restrict__ obj,
                      float* __restrict__ scores) {
    __shared__ unsigned skey[NPX];
    const int b   = blockIdx.y;
    const int tid = threadIdx.x;
    const float* p = obj + b * NPX;

    for (int i = tid; i < NPX; i += 512) {
        unsigned u = __float_as_uint(p[i]);
        skey[i] = u ^ (unsigned)(((int)u >> 31) | 0x80000000);
    }
    __syncthreads();

    const int e = blockIdx.x * 64 + (tid >> 3);
    const int s = tid & 7;
    const unsigned me = skey[e];

    int cnt = 0;
#pragma unroll 8
    for (int t = 0; t < 512; t++) {
        const int i = s + (t << 3);
        const unsigned ki = skey[i];
        cnt += (ki > me) || (ki == me && i < e);
    }
    cnt += __shfl_down_sync(0xffffffffu, cnt, 4);
    cnt += __shfl_down_sync(0xffffffffu, cnt, 2);
    cnt += __shfl_down_sync(0xffffffffu, cnt, 1);

    if (s == 0 && cnt < KTOP) {
        const float v = p[e];
        scores[b * KTOP + cnt] = frcp(1.0f + __expf(-v));
        g_topk_idx[b * KTOP + cnt] = e;
    }
}

// ---------------------------------------------------------------------------
// Kernel 2: one block per (b, k). Phase 1: gather the 36 weights at the
// selected position, compute the 64x64 group-product mask into SMEM
//   mask = 1 / prod_g (1 + exp(-(w_g . enc + b_g)))
// Weights are re-read from SMEM (volatile -> stays LDS, keeps regs low for
// occupancy). Phase 2: 4x clamp-to-edge bilinear upsample streamed to GMEM.
// ---------------------------------------------------------------------------
__global__ __launch_bounds__(256, 6)
void mask_kernel(const float* __restrict__ enc,   // (NB, NE, 64, 64)
                 const float* __restrict__ wts,   // (NB, NCH, 64, 64)
                 float* __restrict__ out) {       // (NB, KTOP, 256, 256)
    __shared__ float low[NPX];
    __shared__ float swt[NCH];

    const int k   = blockIdx.x;
    const int b   = blockIdx.y;
    const int tid = threadIdx.x;

    const int pos = g_topk_idx[b * KTOP + k];
    if (tid < NCH) swt[tid] = wts[(b * NCH + tid) * NPX + pos];
    __syncthreads();

    const volatile float* vw = swt;   // force LDS reads, keep registers low
    const float2* encb = (const float2*)(enc + b * NE * NPX);

#pragma unroll
    for (int it = 0; it < 8; it++) {
        const int q = tid + it * 256;        // float2 index into 64x64 plane
        float2 ev[NE];
#pragma unroll
        for (int e = 0; e < NE; e++)
            ev[e] = __ldg(encb + e * (NPX / 2) + q);

        float px = 1.f, py = 1.f;
#pragma unroll
        for (int g = 0; g < NG; g++) {
            float ax = vw[g * (NE + 1) + NE];
            float ay = ax;
#pragma unroll
            for (int e = 0; e < NE; e++) {
                const float w = vw[g * (NE + 1) + e];
                ax = fmaf(w, ev[e].x, ax);
                ay = fmaf(w, ev[e].y, ay);
            }
            px *= 1.f + __expf(-ax);
            py *= 1.f + __expf(-ay);
        }
        ((float2*)low)[q] = make_float2(frcp(px), frcp(py));
    }
    __syncthreads();

    // Phase 2: bilinear 64->256. Warp w owns output rows [32w, 32w+32);
    // lanes stride columns -> conflict-free LDS, coalesced STG.128.
    float* obase = out + ((size_t)(b * KTOP + k)) * (OUTW * OUTW);
    const int warp = tid >> 5, lane = tid & 31;

#pragma unroll 1
    for (int r = 0; r < 32; r++) {
        const int oy = warp * 32 + r;
        const float yf  = oy * 0.25f - 0.375f;
        const float y0f = floorf(yf);
        const float fy  = yf - y0f;
        int y0 = (int)y0f;     if (y0 < 0)  y0 = 0;
        int y1 = (int)y0f + 1; if (y1 > 63) y1 = 63;
        const float* r0 = low + y0 * 64;
        const float* r1 = low + y1 * 64;
        float4* orow = (float4*)(obase + oy * OUTW);
#pragma unroll
        for (int c = 0; c < 2; c++) {
            const int j  = lane + c * 32;
            const int jp = (j == 0)  ? 0  : j - 1;
            const int jn = (j == 63) ? 63 : j + 1;
            const float vp = fmaf(fy, r1[jp] - r0[jp], r0[jp]);
            const float vc = fmaf(fy, r1[j]  - r0[j],  r0[j]);
            const float vn = fmaf(fy, r1[jn] - r0[jn], r0[jn]);
            float4 o;
            o.x = 0.375f * vp + 0.625f * vc;
            o.y = 0.125f * vp + 0.875f * vc;
            o.z = 0.875f * vc + 0.125f * vn;
            o.w = 0.625f * vc + 0.375f * vn;
            __stcs(orow + j, o);
        }
    }
}

// ---------------------------------------------------------------------------
extern "C" void kernel_launch(void* const* d_in, const int* in_sizes, int n_in,
                              void* d_out, int out_size) {
    const float* obj = (const float*)d_in[0];  // objectness_logits (2,1,64,64)
    const float* enc = (const float*)d_in[1];  // mask_encodings   (2,8,64,64)
    const float* wts = (const float*)d_in[2];  // weights          (2,36,64,64)
    float* out    = (float*)d_out;             // m (2,700,256,256) then scores (2,700)
    float* scores = out + (size_t)NB * KTOP * OUTW * OUTW;

    dim3 tg(64, NB);
    topk_rank_kernel<<<tg, 512>>>(obj, scores);
    dim3 grid(KTOP, NB);
    mask_kernel<<<grid, 256>>>(enc, wts, out);
}